// round 11
// baseline (speedup 1.0000x reference)
#include <cuda_runtime.h>
#include <cstdint>

// Problem constants (fixed by setup_inputs)
#define Nn     4
#define Cc     64
#define Hh     192
#define Ww     192
#define OUTC   3
#define Ss     4
#define SS2    16
#define CK     576         // C*9
#define WCOLS  48          // s*s*outC
#define HIDDEN 256
#define M2     1728
#define HOUT   768
#define WOUT   768

// Dynamic conv weights, g_w[k][sp*3+o], k = c*9 + i*3 + j
__device__ float g_w[CK * WCOLS];

// ---------------------------------------------------------------------------
// Stage 1: Pos2Weight MLP. grid = (16 subpixels, 8 m-chunks), block = 256.
// ---------------------------------------------------------------------------
__global__ void mlp_kernel(const float* __restrict__ W1, const float* __restrict__ b1,
                           const float* __restrict__ W2, const float* __restrict__ b2) {
    __shared__ float hidden[HIDDEN];
    const int sp = blockIdx.x;
    const int chunk = blockIdx.y;
    const int tid = threadIdx.x;

    const float p0 = 0.25f;
    const float p1 = (float)(sp >> 2) * 0.25f;
    const float p2 = (float)(sp & 3) * 0.25f;

    float h = fmaf(p0, W1[tid], fmaf(p1, W1[256 + tid], fmaf(p2, W1[512 + tid], b1[tid])));
    hidden[tid] = fmaxf(h, 0.0f);
    __syncthreads();

    if (tid < 216) {
        const int m = chunk * 216 + tid;
        float sum = b2[m];
        #pragma unroll 8
        for (int j = 0; j < HIDDEN; ++j)
            sum = fmaf(hidden[j], W2[j * M2 + m], sum);
        const int k = m / 3;
        const int o = m - k * 3;
        g_w[k * WCOLS + sp * 3 + o] = sum;
    }
}

// ---------------------------------------------------------------------------
// f32x2 packed-math helpers
// ---------------------------------------------------------------------------
typedef unsigned long long u64;

__device__ __forceinline__ u64 f2dup(float v) {
    u64 r;
    asm("mov.b64 %0, {%1, %1};" : "=l"(r) : "f"(v));
    return r;
}
__device__ __forceinline__ u64 ffma2(u64 a, u64 b, u64 c) {
    u64 d;
    asm("fma.rn.f32x2 %0, %1, %2, %3;" : "=l"(d) : "l"(a), "l"(b), "l"(c));
    return d;
}
__device__ __forceinline__ void f2unpack(u64 v, float& lo, float& hi) {
    asm("mov.b64 {%0, %1}, %2;" : "=f"(lo), "=f"(hi) : "l"(v));
}

// ---------------------------------------------------------------------------
// Stage 2: fused dynamic conv + pixel shuffle.
// Tile 32x16 px, grid (6, 12, 4); 512 threads (16 warps, 4 warps/SMSP).
//   warp = (wq = wid>>2 row band, og = wid&3 col group)  -> og warp-uniform
//   thread = 4x1 pixel strip (rows wq*4..+4, col = lane) x 12 cols
//   channels processed in 2 phases of 32 (smem can't hold all 64)
// smem: weights 27648 f + input chunk 32*18*36 = 20736 f  (193,536 B)
// ---------------------------------------------------------------------------
#define TW 32
#define TH 16
#define PH 32                           // channels per phase
#define SXROW 36
#define SXC (18 * SXROW)                // 648
#define SX_FLOATS (PH * SXC)            // 20736
#define SW_FLOATS (CK * WCOLS)          // 27648
#define STAGE_FLOATS (OUTC * 64 * 128)  // 24576
#define SMEM_BYTES ((SW_FLOATS + SX_FLOATS) * 4)

__global__ void __launch_bounds__(512, 1)
conv_kernel(const float* __restrict__ in, float* __restrict__ out) {
    extern __shared__ float smem[];
    float* sw = smem;                   // [576][48]
    float* sx = smem + SW_FLOATS;       // [32][18][36] (34 cols valid)

    const int tw = blockIdx.x, th = blockIdx.y, n = blockIdx.z;
    const int tid = threadIdx.x;

    // --- load weights (float4, coalesced) ---
    {
        const float4* gw4 = (const float4*)g_w;
        float4* sw4 = (float4*)sw;
        for (int i = tid; i < SW_FLOATS / 4; i += 512) sw4[i] = gw4[i];
    }

    const int wid  = tid >> 5;
    const int lane = tid & 31;
    const int og   = wid & 3;           // warp-uniform col group: cols [og*12, og*12+12)
    const int wq   = wid >> 2;          // 4-row band: rows [wq*4, wq*4+4)

    u64 acc[4][6];
    #pragma unroll
    for (int r = 0; r < 4; ++r)
        #pragma unroll
        for (int cp = 0; cp < 6; ++cp) acc[r][cp] = 0ull;

    const int gh0 = th * TH - 1, gw0 = tw * TW - 1;

    #pragma unroll 1
    for (int ph = 0; ph < 2; ++ph) {
        __syncthreads();   // sx free (prev phase fully consumed / first entry orders sw too)

        // --- load 18x34 halo chunk for channels [ph*32, ph*32+32), stride 36 ---
        {
            const float* inb = in + ((size_t)n * Cc + ph * PH) * Hh * Ww;
            for (int i = tid; i < PH * 18 * 34; i += 512) {
                int c = i / (18 * 34), r = i - c * (18 * 34);
                int lh = r / 34, lw = r - lh * 34;
                int gh = gh0 + lh, gw = gw0 + lw;
                float v = 0.0f;
                if ((unsigned)gh < (unsigned)Hh && (unsigned)gw < (unsigned)Ww)
                    v = inb[(c * Hh + gh) * Ww + gw];
                sx[c * SXC + lh * SXROW + lw] = v;
            }
        }
        __syncthreads();

        const float* xp0 = sx + wq * 4 * SXROW + lane;
        const float* wp0 = sw + (ph * PH) * 9 * WCOLS + og * 12;

        #pragma unroll 1
        for (int c = 0; c < PH; ++c) {
            // 6x3 input patch, broadcast-packed into f32x2
            const float* xp = xp0 + c * SXC;
            u64 P[6][3];
            #pragma unroll
            for (int rr = 0; rr < 6; ++rr)
                #pragma unroll
                for (int qq = 0; qq < 3; ++qq)
                    P[rr][qq] = f2dup(xp[rr * SXROW + qq]);

            const float* wc = wp0 + c * 9 * WCOLS;
            #pragma unroll
            for (int i = 0; i < 3; ++i) {
                #pragma unroll
                for (int j = 0; j < 3; ++j) {
                    const ulonglong2* wv = (const ulonglong2*)(wc + (i * 3 + j) * WCOLS);
                    ulonglong2 a = wv[0], b = wv[1], d = wv[2];
                    u64 Wp[6] = {a.x, a.y, b.x, b.y, d.x, d.y};
                    #pragma unroll
                    for (int r = 0; r < 4; ++r)
                        #pragma unroll
                        for (int cp = 0; cp < 6; ++cp)
                            acc[r][cp] = ffma2(P[i + r][j], Wp[cp], acc[r][cp]);
                }
            }
        }
    }

    __syncthreads();   // all smem free; reuse as output staging
    float* stage = smem;                // [3*64 rows][128 floats]

    // --- scatter accumulators into pixel-shuffled staging layout ---
    // rowid = o*64 + hl*4 + si (si == og); col = wl*4 + sj
    #pragma unroll
    for (int r = 0; r < 4; ++r) {
        const int hl = wq * 4 + r, wl = lane;
        #pragma unroll
        for (int cp = 0; cp < 6; ++cp) {
            float lo, hi;
            f2unpack(acc[r][cp], lo, hi);
            #pragma unroll
            for (int e = 0; e < 2; ++e) {
                const int col = og * 12 + 2 * cp + e;   // = sp*3 + o
                const int sp = col / 3;
                const int o  = col - sp * 3;
                const int sj = sp & 3;
                stage[(o * 64 + hl * 4 + og) * 128 + wl * 4 + sj] = (e == 0) ? lo : hi;
            }
        }
    }
    __syncthreads();

    // --- coalesced float4 stores: each stage row is 128 contiguous output floats ---
    {
        float* outb = out + (size_t)n * OUTC * HOUT * WOUT;
        const float4* st4 = (const float4*)stage;
        #pragma unroll
        for (int v = tid; v < STAGE_FLOATS / 4; v += 512) {
            const int flat = v * 4;
            const int rowid = flat >> 7;        // o*64 + hl*4 + si
            const int cc = flat & 127;
            const int o = rowid >> 6;
            const int rr2 = rowid & 63;
            const int hl = rr2 >> 2;
            const int si = rr2 & 3;
            const int gh = (th * TH + hl) * Ss + si;
            const int gw = tw * TW * Ss + cc;
            *(float4*)(outb + ((size_t)o * HOUT + gh) * WOUT + gw) = st4[v];
        }
    }
}

// ---------------------------------------------------------------------------
extern "C" void kernel_launch(void* const* d_in, const int* in_sizes, int n_in,
                              void* d_out, int out_size) {
    const float* x  = (const float*)d_in[0];
    const float* W1 = (const float*)d_in[1];
    const float* b1 = (const float*)d_in[2];
    const float* W2 = (const float*)d_in[3];
    const float* b2 = (const float*)d_in[4];
    float* out = (float*)d_out;

    mlp_kernel<<<dim3(SS2, 8), 256>>>(W1, b1, W2, b2);

    cudaFuncSetAttribute(conv_kernel, cudaFuncAttributeMaxDynamicSharedMemorySize, SMEM_BYTES);
    conv_kernel<<<dim3(Ww / TW, Hh / TH, Nn), 512, SMEM_BYTES>>>(x, out);
}

// round 12
// speedup vs baseline: 1.0041x; 1.0041x over previous
#include <cuda_runtime.h>
#include <cstdint>

// Problem constants (fixed by setup_inputs)
#define Nn     4
#define Cc     64
#define Hh     192
#define Ww     192
#define OUTC   3
#define Ss     4
#define SS2    16
#define CK     576         // C*9
#define WCOLS  48          // s*s*outC
#define HIDDEN 256
#define M2     1728
#define HOUT   768
#define WOUT   768

// Dynamic conv weights, g_w[k][sp*3+o], k = c*9 + i*3 + j
__device__ float g_w[CK * WCOLS];

// ---------------------------------------------------------------------------
// Stage 1: Pos2Weight MLP. grid = (16 subpixels, 8 m-chunks), block = 256.
// ---------------------------------------------------------------------------
__global__ void mlp_kernel(const float* __restrict__ W1, const float* __restrict__ b1,
                           const float* __restrict__ W2, const float* __restrict__ b2) {
    __shared__ float hidden[HIDDEN];
    const int sp = blockIdx.x;
    const int chunk = blockIdx.y;
    const int tid = threadIdx.x;

    const float p0 = 0.25f;
    const float p1 = (float)(sp >> 2) * 0.25f;
    const float p2 = (float)(sp & 3) * 0.25f;

    float h = fmaf(p0, W1[tid], fmaf(p1, W1[256 + tid], fmaf(p2, W1[512 + tid], b1[tid])));
    hidden[tid] = fmaxf(h, 0.0f);
    __syncthreads();

    if (tid < 216) {
        const int m = chunk * 216 + tid;
        float sum = b2[m];
        #pragma unroll 8
        for (int j = 0; j < HIDDEN; ++j)
            sum = fmaf(hidden[j], W2[j * M2 + m], sum);
        const int k = m / 3;
        const int o = m - k * 3;
        g_w[k * WCOLS + sp * 3 + o] = sum;
    }
}

// ---------------------------------------------------------------------------
// f32x2 packed-math helpers
// ---------------------------------------------------------------------------
typedef unsigned long long u64;

__device__ __forceinline__ u64 f2dup(float v) {
    u64 r;
    asm("mov.b64 %0, {%1, %1};" : "=l"(r) : "f"(v));
    return r;
}
__device__ __forceinline__ u64 ffma2(u64 a, u64 b, u64 c) {
    u64 d;
    asm("fma.rn.f32x2 %0, %1, %2, %3;" : "=l"(d) : "l"(a), "l"(b), "l"(c));
    return d;
}
__device__ __forceinline__ void f2unpack(u64 v, float& lo, float& hi) {
    asm("mov.b64 {%0, %1}, %2;" : "=f"(lo), "=f"(hi) : "l"(v));
}

// ---------------------------------------------------------------------------
// Stage 2: fused dynamic conv + pixel shuffle.
// Tile 32x16 px, grid (6, 12, 4); 512 threads (16 warps, 4 warps/SMSP).
//   warp = (wq = wid>>2 row band, og = wid&3 col group)  -> og warp-uniform
//   thread = 4x1 pixel strip (rows wq*4..+4, col = lane) x 12 cols
//   channels processed in 2 phases of 32 (smem can't hold all 64)
// smem: weights 27648 f + input chunk 32*18*36 = 20736 f  (193,536 B)
// ---------------------------------------------------------------------------
#define TW 32
#define TH 16
#define PH 32                           // channels per phase
#define SXROW 36
#define SXC (18 * SXROW)                // 648
#define SX_FLOATS (PH * SXC)            // 20736
#define SW_FLOATS (CK * WCOLS)          // 27648
#define STAGE_FLOATS (OUTC * 64 * 128)  // 24576
#define SMEM_BYTES ((SW_FLOATS + SX_FLOATS) * 4)

__global__ void __launch_bounds__(512, 1)
conv_kernel(const float* __restrict__ in, float* __restrict__ out) {
    extern __shared__ float smem[];
    float* sw = smem;                   // [576][48]
    float* sx = smem + SW_FLOATS;       // [32][18][36] (34 cols valid)

    const int tw = blockIdx.x, th = blockIdx.y, n = blockIdx.z;
    const int tid = threadIdx.x;

    // --- load weights (float4, coalesced) ---
    {
        const float4* gw4 = (const float4*)g_w;
        float4* sw4 = (float4*)sw;
        for (int i = tid; i < SW_FLOATS / 4; i += 512) sw4[i] = gw4[i];
    }

    const int wid  = tid >> 5;
    const int lane = tid & 31;
    const int og   = wid & 3;           // warp-uniform col group: cols [og*12, og*12+12)
    const int wq   = wid >> 2;          // 4-row band: rows [wq*4, wq*4+4)

    u64 acc[4][6];
    #pragma unroll
    for (int r = 0; r < 4; ++r)
        #pragma unroll
        for (int cp = 0; cp < 6; ++cp) acc[r][cp] = 0ull;

    const int gh0 = th * TH - 1, gw0 = tw * TW - 1;

    #pragma unroll 1
    for (int ph = 0; ph < 2; ++ph) {
        __syncthreads();   // sx free (prev phase fully consumed / first entry orders sw too)

        // --- load 18x34 halo chunk for channels [ph*32, ph*32+32), stride 36 ---
        {
            const float* inb = in + ((size_t)n * Cc + ph * PH) * Hh * Ww;
            for (int i = tid; i < PH * 18 * 34; i += 512) {
                int c = i / (18 * 34), r = i - c * (18 * 34);
                int lh = r / 34, lw = r - lh * 34;
                int gh = gh0 + lh, gw = gw0 + lw;
                float v = 0.0f;
                if ((unsigned)gh < (unsigned)Hh && (unsigned)gw < (unsigned)Ww)
                    v = inb[(c * Hh + gh) * Ww + gw];
                sx[c * SXC + lh * SXROW + lw] = v;
            }
        }
        __syncthreads();

        const float* xp0 = sx + wq * 4 * SXROW + lane;
        const float* wp0 = sw + (ph * PH) * 9 * WCOLS + og * 12;

        #pragma unroll 1
        for (int c = 0; c < PH; ++c) {
            // 6x3 input patch, broadcast-packed into f32x2
            const float* xp = xp0 + c * SXC;
            u64 P[6][3];
            #pragma unroll
            for (int rr = 0; rr < 6; ++rr)
                #pragma unroll
                for (int qq = 0; qq < 3; ++qq)
                    P[rr][qq] = f2dup(xp[rr * SXROW + qq]);

            const float* wc = wp0 + c * 9 * WCOLS;
            #pragma unroll
            for (int i = 0; i < 3; ++i) {
                #pragma unroll
                for (int j = 0; j < 3; ++j) {
                    const ulonglong2* wv = (const ulonglong2*)(wc + (i * 3 + j) * WCOLS);
                    ulonglong2 a = wv[0], b = wv[1], d = wv[2];
                    u64 Wp[6] = {a.x, a.y, b.x, b.y, d.x, d.y};
                    #pragma unroll
                    for (int r = 0; r < 4; ++r)
                        #pragma unroll
                        for (int cp = 0; cp < 6; ++cp)
                            acc[r][cp] = ffma2(P[i + r][j], Wp[cp], acc[r][cp]);
                }
            }
        }
    }

    __syncthreads();   // all smem free; reuse as output staging
    float* stage = smem;                // [3*64 rows][128 floats]

    // --- scatter accumulators into pixel-shuffled staging layout ---
    // rowid = o*64 + hl*4 + si (si == og); col = wl*4 + sj
    #pragma unroll
    for (int r = 0; r < 4; ++r) {
        const int hl = wq * 4 + r, wl = lane;
        #pragma unroll
        for (int cp = 0; cp < 6; ++cp) {
            float lo, hi;
            f2unpack(acc[r][cp], lo, hi);
            #pragma unroll
            for (int e = 0; e < 2; ++e) {
                const int col = og * 12 + 2 * cp + e;   // = sp*3 + o
                const int sp = col / 3;
                const int o  = col - sp * 3;
                const int sj = sp & 3;
                stage[(o * 64 + hl * 4 + og) * 128 + wl * 4 + sj] = (e == 0) ? lo : hi;
            }
        }
    }
    __syncthreads();

    // --- coalesced float4 stores: each stage row is 128 contiguous output floats ---
    {
        float* outb = out + (size_t)n * OUTC * HOUT * WOUT;
        const float4* st4 = (const float4*)stage;
        #pragma unroll
        for (int v = tid; v < STAGE_FLOATS / 4; v += 512) {
            const int flat = v * 4;
            const int rowid = flat >> 7;        // o*64 + hl*4 + si
            const int cc = flat & 127;
            const int o = rowid >> 6;
            const int rr2 = rowid & 63;
            const int hl = rr2 >> 2;
            const int si = rr2 & 3;
            const int gh = (th * TH + hl) * Ss + si;
            const int gw = tw * TW * Ss + cc;
            *(float4*)(outb + ((size_t)o * HOUT + gh) * WOUT + gw) = st4[v];
        }
    }
}

// ---------------------------------------------------------------------------
extern "C" void kernel_launch(void* const* d_in, const int* in_sizes, int n_in,
                              void* d_out, int out_size) {
    const float* x  = (const float*)d_in[0];
    const float* W1 = (const float*)d_in[1];
    const float* b1 = (const float*)d_in[2];
    const float* W2 = (const float*)d_in[3];
    const float* b2 = (const float*)d_in[4];
    float* out = (float*)d_out;

    mlp_kernel<<<dim3(SS2, 8), 256>>>(W1, b1, W2, b2);

    cudaFuncSetAttribute(conv_kernel, cudaFuncAttributeMaxDynamicSharedMemorySize, SMEM_BYTES);
    conv_kernel<<<dim3(Ww / TW, Hh / TH, Nn), 512, SMEM_BYTES>>>(x, out);
}